// round 15
// baseline (speedup 1.0000x reference)
#include <cuda_runtime.h>
#include <cuda_bf16.h>
#include <cstdint>
#include <cstddef>

// ============================================================================
// CausalAttentionLayer, split-kernel design (HMMA mma.sync; tcgen05 is
// feature-gated off because harness PTX targets sm_103 without the 'a').
//
//   S = Q K^T (no scaling); P = softmax(S, FULL row) * strict-lower mask;
//   O = P V.
// Fixed exp shift (40) => no online softmax.
//
// Round-14: prep_all + s_kernel are byte-identical to round-11 (186.4us).
// pv_kernel redesigned: CTA = (b, qx) covers ALL 256 cm columns, so the four
// cm-quarter warps re-reading the same P fragment hit L1 instead of L2 —
// P L2 traffic drops 4x (302 MB -> 75 MB). V staged as 256cm x 32key chunks
// (stride-40 rows, conflict-free ldsm), double-buffered, 2 CTAs/SM.
// ============================================================================

#define BATCH 32
#define NSEQ  1024
#define CD    128
#define CMD   256
#define NKT   8
#define SHIFT 40.0f

#define SQ    136                    // s_kernel smem row stride (bf16)

// ---- s_kernel smem ----
#define S_OQH 0                      // Q hi: 64 x 128 -> 64*136*2 = 17408
#define S_OQL 17408
#define S_OKH 34816                  // K hi: 128 x 128 -> 34816
#define S_OKL 69632
#define S_ODS 104448                 // denom staging: 128 floats
#define S_SMEM (104448 + 512)

// ---- pv_kernel smem: 2 buffers, each Vh+Vl of a 256cm x 32key chunk ----
#define PVS    40                    // pv smem row stride (bf16): 32 keys + 8 pad
#define PV_MAT (256 * PVS * 2)       // 20480 B per matrix (256 cm rows)
#define PV_BUF (2 * PV_MAT)          // 40960 B (Vh + Vl)
#define PV_SMEM (2 * PV_BUF)         // 81920 B -> 2 CTAs/SM

// ---------------- scratch ----------------
__device__ uint4 g_Qh[BATCH*NSEQ*CD/8];
__device__ uint4 g_Ql[BATCH*NSEQ*CD/8];
__device__ uint4 g_Kh[BATCH*NSEQ*CD/8];
__device__ uint4 g_Kl[BATCH*NSEQ*CD/8];
__device__ uint4 g_Vth[BATCH*CMD*NSEQ/8];
__device__ uint4 g_Vtl[BATCH*CMD*NSEQ/8];
// P fragments: [b][qx 16][kt 8][rg 4][s 8][lane 32] -> uint4 (a0..a3)
__device__ uint4 g_Ph[BATCH*16*8*4*8*32];
__device__ uint4 g_Pl[BATCH*16*8*4*8*32];
__device__ float g_d[BATCH*NSEQ];

// ---------------- helpers ----------------
static __device__ __forceinline__ uint32_t smem_u32(const void* p) {
    uint32_t a;
    asm("{ .reg .u64 t; cvta.to.shared.u64 t, %1; cvt.u32.u64 %0, t; }"
        : "=r"(a) : "l"(p));
    return a;
}

static __device__ __forceinline__ void ldsm4(uint32_t r[4], uint32_t addr) {
    asm volatile("ldmatrix.sync.aligned.m8n8.x4.shared.b16 {%0,%1,%2,%3}, [%4];"
                 : "=r"(r[0]), "=r"(r[1]), "=r"(r[2]), "=r"(r[3]) : "r"(addr));
}

static __device__ __forceinline__ void mma16816(float c[4],
                                                uint32_t a0, uint32_t a1,
                                                uint32_t a2, uint32_t a3,
                                                uint32_t b0, uint32_t b1) {
    asm volatile(
        "mma.sync.aligned.m16n8k16.row.col.f32.bf16.bf16.f32 "
        "{%0,%1,%2,%3}, {%4,%5,%6,%7}, {%8,%9}, {%0,%1,%2,%3};"
        : "+f"(c[0]), "+f"(c[1]), "+f"(c[2]), "+f"(c[3])
        : "r"(a0), "r"(a1), "r"(a2), "r"(a3), "r"(b0), "r"(b1));
}

static __device__ __forceinline__ uint32_t pack2(float a, float b) {
    __nv_bfloat162 t = __floats2bfloat162_rn(a, b);
    uint32_t r;
    memcpy(&r, &t, 4);
    return r;
}

static __device__ __forceinline__ void cpa16(uint32_t dst, const void* src) {
    asm volatile("cp.async.cg.shared.global [%0], [%1], 16;"
                 :: "r"(dst), "l"(src));
}
#define CP_COMMIT() asm volatile("cp.async.commit_group;" ::: "memory")
#define CP_WAIT(n)  asm volatile("cp.async.wait_group %0;" :: "n"(n) : "memory")

// ---------------- kernel 1: fused prep (hi/lo split + V transpose) ----------
__global__ void prep_all(const float* __restrict__ q, const float* __restrict__ k,
                         const float* __restrict__ v) {
    __shared__ float t[32][33];
    const int bid = blockIdx.x, tid = threadIdx.x;
    if (bid < 4096) {
        int i = bid * 256 + tid;
        float4 a = ((const float4*)q)[i];
        float4 bb = ((const float4*)k)[i];
        float hx, hy, hz, hw;
        uint2 h, l;
        hx = __bfloat162float(__float2bfloat16(a.x));
        hy = __bfloat162float(__float2bfloat16(a.y));
        hz = __bfloat162float(__float2bfloat16(a.z));
        hw = __bfloat162float(__float2bfloat16(a.w));
        h.x = pack2(hx, hy); h.y = pack2(hz, hw);
        l.x = pack2(a.x - hx, a.y - hy); l.y = pack2(a.z - hz, a.w - hw);
        ((uint2*)g_Qh)[i] = h; ((uint2*)g_Ql)[i] = l;
        hx = __bfloat162float(__float2bfloat16(bb.x));
        hy = __bfloat162float(__float2bfloat16(bb.y));
        hz = __bfloat162float(__float2bfloat16(bb.z));
        hw = __bfloat162float(__float2bfloat16(bb.w));
        h.x = pack2(hx, hy); h.y = pack2(hz, hw);
        l.x = pack2(bb.x - hx, bb.y - hy); l.y = pack2(bb.z - hz, bb.w - hw);
        ((uint2*)g_Kh)[i] = h; ((uint2*)g_Kl)[i] = l;
    } else {
        int vb = bid - 4096;                 // 0..8191
        int b  = vb >> 8;
        int c0 = ((vb >> 5) & 7) * 32;
        int k0 = (vb & 31) * 32;
        int tx = tid & 31, ty = tid >> 5;    // (32, 8)
        #pragma unroll
        for (int r = 0; r < 4; r++)
            t[ty + 8 * r][tx] =
                v[((size_t)b * NSEQ + k0 + ty + 8 * r) * CMD + c0 + tx];
        __syncthreads();
        __nv_bfloat16* oh = (__nv_bfloat16*)g_Vth;
        __nv_bfloat16* ol = (__nv_bfloat16*)g_Vtl;
        #pragma unroll
        for (int r = 0; r < 4; r++) {
            float x = t[tx][ty + 8 * r];
            __nv_bfloat16 hh = __float2bfloat16(x);
            size_t o = ((size_t)b * CMD + c0 + ty + 8 * r) * NSEQ + k0 + tx;
            oh[o] = hh;
            ol[o] = __float2bfloat16(x - __bfloat162float(hh));
        }
    }
}

// ---------------- kernel 2: S + softmax -> P fragments + denominators -------
// (round-11 version, verbatim)
__global__ __launch_bounds__(256, 2)
void s_kernel() {
    extern __shared__ uint8_t sm[];
    const uint32_t smb = smem_u32(sm);
    const int tid  = threadIdx.x;
    const int warp = tid >> 5, lane = tid & 31;
    const int rg   = warp & 3;            // row group: rows rg*16..+15
    const int kh   = warp >> 2;           // key half: keys kh*64..+63
    const int g    = lane >> 2, t = lane & 3;
    const int qx   = blockIdx.x;          // 64-row q tile 0..15
    const int b    = blockIdx.y;
    const int q0   = qx * 64;

    const __nv_bfloat16* pQh = (const __nv_bfloat16*)g_Qh;
    const __nv_bfloat16* pQl = (const __nv_bfloat16*)g_Ql;
    const __nv_bfloat16* pKh = (const __nv_bfloat16*)g_Kh;
    const __nv_bfloat16* pKl = (const __nv_bfloat16*)g_Kl;

    // ---- stage Q (64 rows) + K(0) (128 rows) ----
    {
        const __nv_bfloat16* sQh = pQh + ((size_t)b * NSEQ + q0) * CD;
        const __nv_bfloat16* sQl = pQl + ((size_t)b * NSEQ + q0) * CD;
        #pragma unroll
        for (int it = 0; it < 4; it++) {
            int c = tid + it * 256;       // 1024 granules
            int r = c >> 4, c8 = c & 15;
            cpa16(smb + S_OQH + ((uint32_t)r * SQ + c8 * 8) * 2, sQh + (size_t)r * CD + c8 * 8);
            cpa16(smb + S_OQL + ((uint32_t)r * SQ + c8 * 8) * 2, sQl + (size_t)r * CD + c8 * 8);
        }
        const __nv_bfloat16* sKh = pKh + (size_t)b * NSEQ * CD;
        const __nv_bfloat16* sKl = pKl + (size_t)b * NSEQ * CD;
        #pragma unroll
        for (int it = 0; it < 8; it++) {
            int c = tid + it * 256;       // 2048 granules
            int r = c >> 4, c8 = c & 15;
            cpa16(smb + S_OKH + ((uint32_t)r * SQ + c8 * 8) * 2, sKh + (size_t)r * CD + c8 * 8);
            cpa16(smb + S_OKL + ((uint32_t)r * SQ + c8 * 8) * 2, sKl + (size_t)r * CD + c8 * 8);
        }
    }
    CP_COMMIT();
    CP_WAIT(0);
    __syncthreads();

    // ldmatrix addresses
    const uint32_t aQrow = rg * 16 + (lane & 15);
    const uint32_t aQkof = (lane >> 4) * 8;
    const uint32_t aQh0 = smb + S_OQH + (aQrow * SQ + aQkof) * 2;
    const uint32_t aQl0 = smb + S_OQL + (aQrow * SQ + aQkof) * 2;
    const uint32_t bn  = (lane & 7) + ((lane >= 16) ? 8 : 0);
    const uint32_t bk  = (lane & 8) ? 8 : 0;
    const uint32_t aKh0 = smb + S_OKH + (((uint32_t)kh * 64 + bn) * SQ + bk) * 2;
    const uint32_t aKl0 = smb + S_OKL + (((uint32_t)kh * 64 + bn) * SQ + bk) * 2;

    const int row0 = q0 + rg * 16 + g;
    const int row1 = row0 + 8;
    float d0 = 0.0f, d1 = 0.0f;
    const int ktmax_store = qx >> 1;      // causal tiles: kt <= qx>>1

    for (int kt = 0; kt < NKT; kt++) {
        // ---- S = Qh*Kh + Qh*Kl + Ql*Kh : 16 rows x 64 keys per warp ----
        float Sc[8][4];
        #pragma unroll
        for (int u = 0; u < 8; u++)
            #pragma unroll
            for (int x = 0; x < 4; x++) Sc[u][x] = 0.0f;

        for (int s = 0; s < 8; s++) {
            uint32_t Ah[4], Al[4];
            ldsm4(Ah, aQh0 + s * 32);
            ldsm4(Al, aQl0 + s * 32);
            #pragma unroll
            for (int u = 0; u < 4; u++) {
                uint32_t Bh[4], Bl[4];
                uint32_t off = (uint32_t)u * (16 * SQ * 2) + s * 32;
                ldsm4(Bh, aKh0 + off);
                ldsm4(Bl, aKl0 + off);
                mma16816(Sc[2*u],   Ah[0],Ah[1],Ah[2],Ah[3], Bh[0],Bh[1]);
                mma16816(Sc[2*u],   Ah[0],Ah[1],Ah[2],Ah[3], Bl[0],Bl[1]);
                mma16816(Sc[2*u],   Al[0],Al[1],Al[2],Al[3], Bh[0],Bh[1]);
                mma16816(Sc[2*u+1], Ah[0],Ah[1],Ah[2],Ah[3], Bh[2],Bh[3]);
                mma16816(Sc[2*u+1], Ah[0],Ah[1],Ah[2],Ah[3], Bl[2],Bl[3]);
                mma16816(Sc[2*u+1], Al[0],Al[1],Al[2],Al[3], Bh[2],Bh[3]);
            }
        }
        __syncthreads();                  // all warps done reading K(kt)

        // ---- prefetch K(kt+1); lands while softmax/store runs ----
        if (kt < NKT - 1) {
            const __nv_bfloat16* sKh = pKh + ((size_t)b * NSEQ + (kt + 1) * 128) * CD;
            const __nv_bfloat16* sKl = pKl + ((size_t)b * NSEQ + (kt + 1) * 128) * CD;
            #pragma unroll
            for (int it = 0; it < 8; it++) {
                int c = tid + it * 256;
                int r = c >> 4, c8 = c & 15;
                cpa16(smb + S_OKH + ((uint32_t)r * SQ + c8 * 8) * 2, sKh + (size_t)r * CD + c8 * 8);
                cpa16(smb + S_OKL + ((uint32_t)r * SQ + c8 * 8) * 2, sKl + (size_t)r * CD + c8 * 8);
            }
        }
        CP_COMMIT();

        // ---- exp, denominators, masked P fragments -> gmem ----
        const bool store_p = (kt <= ktmax_store);
        #pragma unroll
        for (int u = 0; u < 4; u++) {
            const int cA = kt * 128 + kh * 64 + u * 16 + 2 * t;
            const int cB = cA + 8;
            float e00 = __expf(Sc[2*u][0] - SHIFT), e01 = __expf(Sc[2*u][1] - SHIFT);
            float e02 = __expf(Sc[2*u][2] - SHIFT), e03 = __expf(Sc[2*u][3] - SHIFT);
            float f00 = __expf(Sc[2*u+1][0] - SHIFT), f01 = __expf(Sc[2*u+1][1] - SHIFT);
            float f02 = __expf(Sc[2*u+1][2] - SHIFT), f03 = __expf(Sc[2*u+1][3] - SHIFT);
            d0 += (e00 + e01) + (f00 + f01);
            d1 += (e02 + e03) + (f02 + f03);
            if (store_p) {
                float p00 = (cA     < row0) ? e00 : 0.0f;
                float p01 = (cA + 1 < row0) ? e01 : 0.0f;
                float p02 = (cA     < row1) ? e02 : 0.0f;
                float p03 = (cA + 1 < row1) ? e03 : 0.0f;
                float q00 = (cB     < row0) ? f00 : 0.0f;
                float q01 = (cB + 1 < row0) ? f01 : 0.0f;
                float q02 = (cB     < row1) ? f02 : 0.0f;
                float q03 = (cB + 1 < row1) ? f03 : 0.0f;
                float h00 = __bfloat162float(__float2bfloat16(p00));
                float h01 = __bfloat162float(__float2bfloat16(p01));
                float h02 = __bfloat162float(__float2bfloat16(p02));
                float h03 = __bfloat162float(__float2bfloat16(p03));
                float i00 = __bfloat162float(__float2bfloat16(q00));
                float i01 = __bfloat162float(__float2bfloat16(q01));
                float i02 = __bfloat162float(__float2bfloat16(q02));
                float i03 = __bfloat162float(__float2bfloat16(q03));
                // fragment index: [b][qx][kt][rg][s = kh*4+u][lane]
                size_t fi = ((((((size_t)b * 16 + qx) * 8 + kt) * 4 + rg) * 8
                              + (kh * 4 + u)) * 32) + lane;
                g_Ph[fi] = make_uint4(pack2(h00, h01), pack2(h02, h03),
                                      pack2(i00, i01), pack2(i02, i03));
                g_Pl[fi] = make_uint4(pack2(p00 - h00, p01 - h01),
                                      pack2(p02 - h02, p03 - h03),
                                      pack2(q00 - i00, q01 - i01),
                                      pack2(q02 - i02, q03 - i03));
            }
        }

        CP_WAIT(0);                       // K(kt+1) landed
        __syncthreads();
    }

    // ---- denominators: quad reduce, cross-key-half combine, store ----
    d0 += __shfl_xor_sync(0xffffffffu, d0, 1);
    d0 += __shfl_xor_sync(0xffffffffu, d0, 2);
    d1 += __shfl_xor_sync(0xffffffffu, d1, 1);
    d1 += __shfl_xor_sync(0xffffffffu, d1, 2);
    float* dsm = (float*)(sm + S_ODS);
    if (t == 0) {
        dsm[kh * 64 + rg * 16 + g]     = d0;
        dsm[kh * 64 + rg * 16 + g + 8] = d1;
    }
    __syncthreads();
    if (tid < 64)
        g_d[(size_t)b * NSEQ + q0 + tid] = dsm[tid] + dsm[64 + tid];
}

// ---------------- kernel 3: O = P V (full-width CTA, L1-deduped P) ----------
// CTA = (b, qx): all 256 cm. 8 warps = 2 row-pairs x 4 cm-quarters. The 4 cmq
// warps of a row-pair load identical P fragments -> L1 hits (1x L2 traffic).
__global__ __launch_bounds__(256, 2)
void pv_kernel(float* __restrict__ outg) {
    extern __shared__ uint8_t sm[];
    const uint32_t smb = smem_u32(sm);
    const int tid  = threadIdx.x;
    const int w    = tid >> 5, lane = tid & 31;
    const int rp   = w & 1;                        // row pair: rg {2rp, 2rp+1}
    const int cmq  = w >> 1;                       // cm quarter 0..3
    const int g    = lane >> 2, t = lane & 3;

    // LPT decode: big qx first
    const int bid = blockIdx.x;                    // 0..511
    const int qx  = 15 - (bid >> 5);
    const int b   = bid & 31;
    const int q0  = qx * 64;
    const int nch = ((qx >> 1) + 1) * 4;           // causal 32-key chunks

    const __nv_bfloat16* pVh = (const __nv_bfloat16*)g_Vth;
    const __nv_bfloat16* pVl = (const __nv_bfloat16*)g_Vtl;

    // stage one V chunk (256 cm rows x 32 keys, hi+lo) into buffer c&1
    auto stageV = [&](int c) {
        const __nv_bfloat16* sh = pVh + (size_t)b * CMD * NSEQ + c * 32;
        const __nv_bfloat16* sl = pVl + (size_t)b * CMD * NSEQ + c * 32;
        const uint32_t base = smb + (c & 1) * PV_BUF;
        #pragma unroll
        for (int it = 0; it < 4; it++) {
            int cc = tid + it * 256;               // 1024 granules per matrix
            int rr = cc >> 2, c8 = cc & 3;         // row 0..255, 4x16B per row
            cpa16(base + ((uint32_t)rr * PVS + c8 * 8) * 2, sh + (size_t)rr * NSEQ + c8 * 8);
            cpa16(base + PV_MAT + ((uint32_t)rr * PVS + c8 * 8) * 2, sl + (size_t)rr * NSEQ + c8 * 8);
        }
    };

    // V ldsm per-lane base (within buffer): lanes<16 -> Vh, >=16 -> Vl,
    // offset to this warp's cm quarter.
    const uint32_t vn = lane & 7;
    const uint32_t vk = (lane & 8) ? 8 : 0;
    const uint32_t aVrel = ((lane < 16) ? 0u : (uint32_t)PV_MAT)
                         + ((uint32_t)cmq * 64 + vn) * (PVS * 2) + vk * 2;

    float O[2][8][4];
    #pragma unroll
    for (int i = 0; i < 2; i++)
        #pragma unroll
        for (int j = 0; j < 8; j++)
            #pragma unroll
            for (int x = 0; x < 4; x++) O[i][j][x] = 0.0f;

    // fragment base: [b][qx][kt][rg][s][lane]; strides kt:1024, rg:256, s:32
    const size_t fbase = ((((size_t)b * 16 + qx) * 8) * 4) * 8 * 32 + lane;
    const int rg0 = rp * 2;

    stageV(0);
    CP_COMMIT();

    for (int c = 0; c < nch; c++) {
        if (c + 1 < nch) {                         // prefetch next chunk
            stageV(c + 1);
            CP_COMMIT();
            CP_WAIT(1);                            // chunk c (oldest) landed
        } else {
            CP_WAIT(0);
        }
        __syncthreads();                           // chunk c visible everywhere

        const int kt = c >> 2;
        const int s0 = (c & 3) * 2;                // two s-steps per chunk
        const uint32_t vbase = smb + (c & 1) * PV_BUF + aVrel;
        #pragma unroll
        for (int step = 0; step < 2; step++) {
            const size_t fi = fbase + (size_t)kt * 1024 + (size_t)rg0 * 256
                            + (size_t)(s0 + step) * 32;
            uint4 Ph0 = g_Ph[fi];                  // warps sharing rp: L1 hits
            uint4 Pl0 = g_Pl[fi];
            uint4 Ph1 = g_Ph[fi + 256];
            uint4 Pl1 = g_Pl[fi + 256];
            #pragma unroll
            for (int j = 0; j < 8; j++) {
                uint32_t Bv[4];                    // [0,1]=Vh k0,k8  [2,3]=Vl
                ldsm4(Bv, vbase + (uint32_t)j * (8 * PVS * 2) + step * 32);
                mma16816(O[0][j], Ph0.x, Ph0.y, Ph0.z, Ph0.w, Bv[0], Bv[1]);
                mma16816(O[0][j], Pl0.x, Pl0.y, Pl0.z, Pl0.w, Bv[0], Bv[1]);
                mma16816(O[0][j], Ph0.x, Ph0.y, Ph0.z, Ph0.w, Bv[2], Bv[3]);
                mma16816(O[1][j], Ph1.x, Ph1.y, Ph1.z, Ph1.w, Bv[0], Bv[1]);
                mma16816(O[1][j], Pl1.x, Pl1.y, Pl1.z, Pl1.w, Bv[0], Bv[1]);
                mma16816(O[1][j], Ph1.x, Ph1.y, Ph1.z, Ph1.w, Bv[2], Bv[3]);
            }
        }
        __syncthreads();                           // done reading buffer c&1
    }

    // ---- epilogue: divide by full-row denominator, store ----
    #pragma unroll
    for (int rgi = 0; rgi < 2; rgi++) {
        const int rg = rg0 + rgi;
        const int row0 = q0 + rg * 16 + g;
        const int row1 = row0 + 8;
        const float i0 = 1.0f / g_d[(size_t)b * NSEQ + row0];
        const float i1 = 1.0f / g_d[(size_t)b * NSEQ + row1];
        const size_t r0o = ((size_t)b * NSEQ + row0) * CMD + cmq * 64;
        const size_t r1o = ((size_t)b * NSEQ + row1) * CMD + cmq * 64;
        #pragma unroll
        for (int j = 0; j < 8; j++) {
            float2 v0, v1;
            v0.x = O[rgi][j][0] * i0; v0.y = O[rgi][j][1] * i0;
            v1.x = O[rgi][j][2] * i1; v1.y = O[rgi][j][3] * i1;
            *(float2*)(outg + r0o + 8 * j + 2 * t) = v0;
            *(float2*)(outg + r1o + 8 * j + 2 * t) = v1;
        }
    }
}

// ---------------- launch ----------------
extern "C" void kernel_launch(void* const* d_in, const int* in_sizes, int n_in,
                              void* d_out, int out_size)
{
    const float* q = (const float*)d_in[0];
    const float* k = (const float*)d_in[1];
    const float* v = (const float*)d_in[2];
    float* out = (float*)d_out;

    cudaFuncSetAttribute(s_kernel,
                         cudaFuncAttributeMaxDynamicSharedMemorySize, S_SMEM);
    cudaFuncSetAttribute(pv_kernel,
                         cudaFuncAttributeMaxDynamicSharedMemorySize, PV_SMEM);

    prep_all<<<4096 + 8192, 256>>>(q, k, v);
    s_kernel<<<dim3(16, BATCH), 256, S_SMEM>>>();
    pv_kernel<<<512, 256, PV_SMEM>>>(out);

    (void)in_sizes; (void)n_in; (void)out_size;
}

// round 16
// speedup vs baseline: 1.1454x; 1.1454x over previous
#include <cuda_runtime.h>
#include <cuda_bf16.h>
#include <cstdint>
#include <cstddef>

// ============================================================================
// CausalAttentionLayer, split-kernel design (HMMA mma.sync; tcgen05 is
// feature-gated off because harness PTX targets sm_103 without the 'a').
//
//   S = Q K^T (no scaling); P = softmax(S, FULL row) * strict-lower mask;
//   O = P V.
// Fixed exp shift (40) => no online softmax.
//
// Round-16: full revert to round-11 (186.4us champion) EXCEPT one isolated
// change in s_kernel: Q-hi ldmatrix fragments hoisted into registers before
// the kt loop (Q is kt-invariant), removing 64 of 640 ldsm per warp from the
// smem crossbar. prep_all and pv_kernel are byte-identical to round-11.
// Lesson bank: pv chunk granularity 128-key >> 64-key >> 32-key (R12-R14);
// pv is a verified local optimum — do not touch.
// ============================================================================

#define BATCH 32
#define NSEQ  1024
#define CD    128
#define CMD   256
#define NKT   8
#define SHIFT 40.0f

#define SQ    136                    // s_kernel smem row stride (bf16)

// ---- s_kernel smem ----
#define S_OQH 0                      // Q hi: 64 x 128 -> 64*136*2 = 17408
#define S_OQL 17408
#define S_OKH 34816                  // K hi: 128 x 128 -> 34816
#define S_OKL 69632
#define S_ODS 104448                 // denom staging: 128 floats
#define S_SMEM (104448 + 512)

// ---- pv_kernel smem: two V buffers (hi+lo 64x128 each), round-11 layout ----
#define PV_BUF 34816                 // per buffer: Vh 17408 + Vl 17408
#define PV_SMEM (2 * PV_BUF)

// ---------------- scratch ----------------
__device__ uint4 g_Qh[BATCH*NSEQ*CD/8];
__device__ uint4 g_Ql[BATCH*NSEQ*CD/8];
__device__ uint4 g_Kh[BATCH*NSEQ*CD/8];
__device__ uint4 g_Kl[BATCH*NSEQ*CD/8];
__device__ uint4 g_Vth[BATCH*CMD*NSEQ/8];
__device__ uint4 g_Vtl[BATCH*CMD*NSEQ/8];
// P fragments: [b][qx 16][kt 8][rg 4][s 8][lane 32] -> uint4 (a0..a3)
__device__ uint4 g_Ph[BATCH*16*8*4*8*32];
__device__ uint4 g_Pl[BATCH*16*8*4*8*32];
__device__ float g_d[BATCH*NSEQ];

// ---------------- helpers ----------------
static __device__ __forceinline__ uint32_t smem_u32(const void* p) {
    uint32_t a;
    asm("{ .reg .u64 t; cvta.to.shared.u64 t, %1; cvt.u32.u64 %0, t; }"
        : "=r"(a) : "l"(p));
    return a;
}

static __device__ __forceinline__ void ldsm4(uint32_t r[4], uint32_t addr) {
    asm volatile("ldmatrix.sync.aligned.m8n8.x4.shared.b16 {%0,%1,%2,%3}, [%4];"
                 : "=r"(r[0]), "=r"(r[1]), "=r"(r[2]), "=r"(r[3]) : "r"(addr));
}

static __device__ __forceinline__ void mma16816(float c[4],
                                                uint32_t a0, uint32_t a1,
                                                uint32_t a2, uint32_t a3,
                                                uint32_t b0, uint32_t b1) {
    asm volatile(
        "mma.sync.aligned.m16n8k16.row.col.f32.bf16.bf16.f32 "
        "{%0,%1,%2,%3}, {%4,%5,%6,%7}, {%8,%9}, {%0,%1,%2,%3};"
        : "+f"(c[0]), "+f"(c[1]), "+f"(c[2]), "+f"(c[3])
        : "r"(a0), "r"(a1), "r"(a2), "r"(a3), "r"(b0), "r"(b1));
}

static __device__ __forceinline__ uint32_t pack2(float a, float b) {
    __nv_bfloat162 t = __floats2bfloat162_rn(a, b);
    uint32_t r;
    memcpy(&r, &t, 4);
    return r;
}

static __device__ __forceinline__ void cpa16(uint32_t dst, const void* src) {
    asm volatile("cp.async.cg.shared.global [%0], [%1], 16;"
                 :: "r"(dst), "l"(src));
}
#define CP_COMMIT() asm volatile("cp.async.commit_group;" ::: "memory")
#define CP_WAIT(n)  asm volatile("cp.async.wait_group %0;" :: "n"(n) : "memory")

// ---------------- kernel 1: fused prep (hi/lo split + V transpose) ----------
// (round-11 version, verbatim)
__global__ void prep_all(const float* __restrict__ q, const float* __restrict__ k,
                         const float* __restrict__ v) {
    __shared__ float t[32][33];
    const int bid = blockIdx.x, tid = threadIdx.x;
    if (bid < 4096) {
        int i = bid * 256 + tid;
        float4 a = ((const float4*)q)[i];
        float4 bb = ((const float4*)k)[i];
        float hx, hy, hz, hw;
        uint2 h, l;
        hx = __bfloat162float(__float2bfloat16(a.x));
        hy = __bfloat162float(__float2bfloat16(a.y));
        hz = __bfloat162float(__float2bfloat16(a.z));
        hw = __bfloat162float(__float2bfloat16(a.w));
        h.x = pack2(hx, hy); h.y = pack2(hz, hw);
        l.x = pack2(a.x - hx, a.y - hy); l.y = pack2(a.z - hz, a.w - hw);
        ((uint2*)g_Qh)[i] = h; ((uint2*)g_Ql)[i] = l;
        hx = __bfloat162float(__float2bfloat16(bb.x));
        hy = __bfloat162float(__float2bfloat16(bb.y));
        hz = __bfloat162float(__float2bfloat16(bb.z));
        hw = __bfloat162float(__float2bfloat16(bb.w));
        h.x = pack2(hx, hy); h.y = pack2(hz, hw);
        l.x = pack2(bb.x - hx, bb.y - hy); l.y = pack2(bb.z - hz, bb.w - hw);
        ((uint2*)g_Kh)[i] = h; ((uint2*)g_Kl)[i] = l;
    } else {
        int vb = bid - 4096;                 // 0..8191
        int b  = vb >> 8;
        int c0 = ((vb >> 5) & 7) * 32;
        int k0 = (vb & 31) * 32;
        int tx = tid & 31, ty = tid >> 5;    // (32, 8)
        #pragma unroll
        for (int r = 0; r < 4; r++)
            t[ty + 8 * r][tx] =
                v[((size_t)b * NSEQ + k0 + ty + 8 * r) * CMD + c0 + tx];
        __syncthreads();
        __nv_bfloat16* oh = (__nv_bfloat16*)g_Vth;
        __nv_bfloat16* ol = (__nv_bfloat16*)g_Vtl;
        #pragma unroll
        for (int r = 0; r < 4; r++) {
            float x = t[tx][ty + 8 * r];
            __nv_bfloat16 hh = __float2bfloat16(x);
            size_t o = ((size_t)b * CMD + c0 + ty + 8 * r) * NSEQ + k0 + tx;
            oh[o] = hh;
            ol[o] = __float2bfloat16(x - __bfloat162float(hh));
        }
    }
}

// ---------------- kernel 2: S + softmax -> P fragments + denominators -------
// round-11 version + ONE change: Q-hi fragments hoisted to registers.
__global__ __launch_bounds__(256, 2)
void s_kernel() {
    extern __shared__ uint8_t sm[];
    const uint32_t smb = smem_u32(sm);
    const int tid  = threadIdx.x;
    const int warp = tid >> 5, lane = tid & 31;
    const int rg   = warp & 3;            // row group: rows rg*16..+15
    const int kh   = warp >> 2;           // key half: keys kh*64..+63
    const int g    = lane >> 2, t = lane & 3;
    const int qx   = blockIdx.x;          // 64-row q tile 0..15
    const int b    = blockIdx.y;
    const int q0   = qx * 64;

    const __nv_bfloat16* pQh = (const __nv_bfloat16*)g_Qh;
    const __nv_bfloat16* pQl = (const __nv_bfloat16*)g_Ql;
    const __nv_bfloat16* pKh = (const __nv_bfloat16*)g_Kh;
    const __nv_bfloat16* pKl = (const __nv_bfloat16*)g_Kl;

    // ---- stage Q (64 rows) + K(0) (128 rows) ----
    {
        const __nv_bfloat16* sQh = pQh + ((size_t)b * NSEQ + q0) * CD;
        const __nv_bfloat16* sQl = pQl + ((size_t)b * NSEQ + q0) * CD;
        #pragma unroll
        for (int it = 0; it < 4; it++) {
            int c = tid + it * 256;       // 1024 granules
            int r = c >> 4, c8 = c & 15;
            cpa16(smb + S_OQH + ((uint32_t)r * SQ + c8 * 8) * 2, sQh + (size_t)r * CD + c8 * 8);
            cpa16(smb + S_OQL + ((uint32_t)r * SQ + c8 * 8) * 2, sQl + (size_t)r * CD + c8 * 8);
        }
        const __nv_bfloat16* sKh = pKh + (size_t)b * NSEQ * CD;
        const __nv_bfloat16* sKl = pKl + (size_t)b * NSEQ * CD;
        #pragma unroll
        for (int it = 0; it < 8; it++) {
            int c = tid + it * 256;       // 2048 granules
            int r = c >> 4, c8 = c & 15;
            cpa16(smb + S_OKH + ((uint32_t)r * SQ + c8 * 8) * 2, sKh + (size_t)r * CD + c8 * 8);
            cpa16(smb + S_OKL + ((uint32_t)r * SQ + c8 * 8) * 2, sKl + (size_t)r * CD + c8 * 8);
        }
    }
    CP_COMMIT();
    CP_WAIT(0);
    __syncthreads();

    // ldmatrix addresses
    const uint32_t aQrow = rg * 16 + (lane & 15);
    const uint32_t aQkof = (lane >> 4) * 8;
    const uint32_t aQh0 = smb + S_OQH + (aQrow * SQ + aQkof) * 2;
    const uint32_t aQl0 = smb + S_OQL + (aQrow * SQ + aQkof) * 2;
    const uint32_t bn  = (lane & 7) + ((lane >= 16) ? 8 : 0);
    const uint32_t bk  = (lane & 8) ? 8 : 0;
    const uint32_t aKh0 = smb + S_OKH + (((uint32_t)kh * 64 + bn) * SQ + bk) * 2;
    const uint32_t aKl0 = smb + S_OKL + (((uint32_t)kh * 64 + bn) * SQ + bk) * 2;

    // ---- hoist Q-hi fragments (kt-invariant) into registers ----
    uint32_t QFh[8][4];
    #pragma unroll
    for (int s = 0; s < 8; s++)
        ldsm4(QFh[s], aQh0 + s * 32);

    const int row0 = q0 + rg * 16 + g;
    const int row1 = row0 + 8;
    float d0 = 0.0f, d1 = 0.0f;
    const int ktmax_store = qx >> 1;      // causal tiles: kt <= qx>>1

    for (int kt = 0; kt < NKT; kt++) {
        // ---- S = Qh*Kh + Qh*Kl + Ql*Kh : 16 rows x 64 keys per warp ----
        float Sc[8][4];
        #pragma unroll
        for (int u = 0; u < 8; u++)
            #pragma unroll
            for (int x = 0; x < 4; x++) Sc[u][x] = 0.0f;

        #pragma unroll
        for (int s = 0; s < 8; s++) {
            uint32_t Al[4];
            ldsm4(Al, aQl0 + s * 32);
            #pragma unroll
            for (int u = 0; u < 4; u++) {
                uint32_t Bh[4], Bl[4];
                uint32_t off = (uint32_t)u * (16 * SQ * 2) + s * 32;
                ldsm4(Bh, aKh0 + off);
                ldsm4(Bl, aKl0 + off);
                mma16816(Sc[2*u],   QFh[s][0],QFh[s][1],QFh[s][2],QFh[s][3], Bh[0],Bh[1]);
                mma16816(Sc[2*u],   QFh[s][0],QFh[s][1],QFh[s][2],QFh[s][3], Bl[0],Bl[1]);
                mma16816(Sc[2*u],   Al[0],Al[1],Al[2],Al[3], Bh[0],Bh[1]);
                mma16816(Sc[2*u+1], QFh[s][0],QFh[s][1],QFh[s][2],QFh[s][3], Bh[2],Bh[3]);
                mma16816(Sc[2*u+1], QFh[s][0],QFh[s][1],QFh[s][2],QFh[s][3], Bl[2],Bl[3]);
                mma16816(Sc[2*u+1], Al[0],Al[1],Al[2],Al[3], Bh[2],Bh[3]);
            }
        }
        __syncthreads();                  // all warps done reading K(kt)

        // ---- prefetch K(kt+1); lands while softmax/store runs ----
        if (kt < NKT - 1) {
            const __nv_bfloat16* sKh = pKh + ((size_t)b * NSEQ + (kt + 1) * 128) * CD;
            const __nv_bfloat16* sKl = pKl + ((size_t)b * NSEQ + (kt + 1) * 128) * CD;
            #pragma unroll
            for (int it = 0; it < 8; it++) {
                int c = tid + it * 256;
                int r = c >> 4, c8 = c & 15;
                cpa16(smb + S_OKH + ((uint32_t)r * SQ + c8 * 8) * 2, sKh + (size_t)r * CD + c8 * 8);
                cpa16(smb + S_OKL + ((uint32_t)r * SQ + c8 * 8) * 2, sKl + (size_t)r * CD + c8 * 8);
            }
        }
        CP_COMMIT();

        // ---- exp, denominators, masked P fragments -> gmem ----
        const bool store_p = (kt <= ktmax_store);
        #pragma unroll
        for (int u = 0; u < 4; u++) {
            const int cA = kt * 128 + kh * 64 + u * 16 + 2 * t;
            const int cB = cA + 8;
            float e00 = __expf(Sc[2*u][0] - SHIFT), e01 = __expf(Sc[2*u][1] - SHIFT);
            float e02 = __expf(Sc[2*u][2] - SHIFT), e03 = __expf(Sc[2*u][3] - SHIFT);
            float f00 = __expf(Sc[2*u+1][0] - SHIFT), f01 = __expf(Sc[2*u+1][1] - SHIFT);
            float f02 = __expf(Sc[2*u+1][2] - SHIFT), f03 = __expf(Sc[2*u+1][3] - SHIFT);
            d0 += (e00 + e01) + (f00 + f01);
            d1 += (e02 + e03) + (f02 + f03);
            if (store_p) {
                float p00 = (cA     < row0) ? e00 : 0.0f;
                float p01 = (cA + 1 < row0) ? e01 : 0.0f;
                float p02 = (cA     < row1) ? e02 : 0.0f;
                float p03 = (cA + 1 < row1) ? e03 : 0.0f;
                float q00 = (cB     < row0) ? f00 : 0.0f;
                float q01 = (cB + 1 < row0) ? f01 : 0.0f;
                float q02 = (cB     < row1) ? f02 : 0.0f;
                float q03 = (cB + 1 < row1) ? f03 : 0.0f;
                float h00 = __bfloat162float(__float2bfloat16(p00));
                float h01 = __bfloat162float(__float2bfloat16(p01));
                float h02 = __bfloat162float(__float2bfloat16(p02));
                float h03 = __bfloat162float(__float2bfloat16(p03));
                float i00 = __bfloat162float(__float2bfloat16(q00));
                float i01 = __bfloat162float(__float2bfloat16(q01));
                float i02 = __bfloat162float(__float2bfloat16(q02));
                float i03 = __bfloat162float(__float2bfloat16(q03));
                // fragment index: [b][qx][kt][rg][s = kh*4+u][lane]
                size_t fi = ((((((size_t)b * 16 + qx) * 8 + kt) * 4 + rg) * 8
                              + (kh * 4 + u)) * 32) + lane;
                g_Ph[fi] = make_uint4(pack2(h00, h01), pack2(h02, h03),
                                      pack2(i00, i01), pack2(i02, i03));
                g_Pl[fi] = make_uint4(pack2(p00 - h00, p01 - h01),
                                      pack2(p02 - h02, p03 - h03),
                                      pack2(q00 - i00, q01 - i01),
                                      pack2(q02 - i02, q03 - i03));
            }
        }

        CP_WAIT(0);                       // K(kt+1) landed
        __syncthreads();
    }

    // ---- denominators: quad reduce, cross-key-half combine, store ----
    d0 += __shfl_xor_sync(0xffffffffu, d0, 1);
    d0 += __shfl_xor_sync(0xffffffffu, d0, 2);
    d1 += __shfl_xor_sync(0xffffffffu, d1, 1);
    d1 += __shfl_xor_sync(0xffffffffu, d1, 2);
    float* dsm = (float*)(sm + S_ODS);
    if (t == 0) {
        dsm[kh * 64 + rg * 16 + g]     = d0;
        dsm[kh * 64 + rg * 16 + g + 8] = d1;
    }
    __syncthreads();
    if (tid < 64)
        g_d[(size_t)b * NSEQ + q0 + tid] = dsm[tid] + dsm[64 + tid];
}

// ---------------- kernel 3: O = P V (pure GEMM) -----------------------------
// (round-11 version, verbatim: 64-cm-quarter CTAs, 128-key double-buffered)
__global__ __launch_bounds__(128, 3)
void pv_kernel(float* __restrict__ outg) {
    extern __shared__ uint8_t sm[];
    const uint32_t smb = smem_u32(sm);
    const int tid  = threadIdx.x;
    const int rg   = tid >> 5, lane = tid & 31;
    const int g    = lane >> 2, t = lane & 3;

    // LPT decode: big qx first
    const int bid = blockIdx.x;                    // 0..2047
    const int qx  = 15 - (bid >> 7);
    const int r   = bid & 127;
    const int cmq = r & 3;                         // 64-cm quarter
    const int b   = r >> 2;
    const int q0  = qx * 64;
    const int nch = (qx >> 1) + 1;                 // causal 128-key chunks

    const __nv_bfloat16* pVh = (const __nv_bfloat16*)g_Vth;
    const __nv_bfloat16* pVl = (const __nv_bfloat16*)g_Vtl;

    // stage one V chunk (64 cm rows x 128 keys, hi+lo) into buffer bi
    auto stageV = [&](int kt, int bi) {
        const __nv_bfloat16* sh = pVh + ((size_t)b * CMD + cmq * 64) * NSEQ + kt * 128;
        const __nv_bfloat16* sl = pVl + ((size_t)b * CMD + cmq * 64) * NSEQ + kt * 128;
        const uint32_t base = smb + bi * PV_BUF;
        #pragma unroll
        for (int it = 0; it < 8; it++) {
            int c = tid + it * 128;                // 1024 granules each
            int rr = c >> 4, c8 = c & 15;
            cpa16(base + ((uint32_t)rr * SQ + c8 * 8) * 2, sh + (size_t)rr * NSEQ + c8 * 8);
            cpa16(base + 17408 + ((uint32_t)rr * SQ + c8 * 8) * 2, sl + (size_t)rr * NSEQ + c8 * 8);
        }
    };

    // V ldsm per-lane base (within a buffer): lanes<16 -> Vh, >=16 -> Vl
    const uint32_t vn = lane & 7;
    const uint32_t vk = (lane & 8) ? 8 : 0;
    const uint32_t aVrel = ((lane < 16) ? 0u : 17408u) + (vn * SQ + vk) * 2;

    float O[8][4];
    #pragma unroll
    for (int j = 0; j < 8; j++)
        #pragma unroll
        for (int x = 0; x < 4; x++) O[j][x] = 0.0f;

    const uint4* __restrict__ basePh =
        g_Ph + (((((size_t)b * 16 + qx) * 8) * 4 + rg) * 8) * 32 + lane;
    const uint4* __restrict__ basePl =
        g_Pl + (((((size_t)b * 16 + qx) * 8) * 4 + rg) * 8) * 32 + lane;
    // per-kt stride in fragments: 4 rg * 8 s * 32 lanes = 1024 uint4

    stageV(0, 0);
    CP_COMMIT();

    for (int kt = 0; kt < nch; kt++) {
        CP_WAIT(0);
        __syncthreads();                           // V(kt) visible everywhere
        if (kt + 1 < nch) {                        // overlap next V with compute
            stageV(kt + 1, (kt + 1) & 1);
            CP_COMMIT();
        }
        const uint32_t vbase = smb + (kt & 1) * PV_BUF + aVrel;
        const uint4* ph = basePh + (size_t)kt * 1024;
        const uint4* pl = basePl + (size_t)kt * 1024;
        #pragma unroll
        for (int s = 0; s < 8; s++) {
            uint4 Ph = ph[s * 32];                 // coalesced LDG.128
            uint4 Pl = pl[s * 32];
            #pragma unroll
            for (int j = 0; j < 8; j++) {
                uint32_t Bv[4];                    // [0,1]=Vh k0,k8  [2,3]=Vl
                ldsm4(Bv, vbase + (uint32_t)j * (8 * SQ * 2) + s * 32);
                mma16816(O[j], Ph.x, Ph.y, Ph.z, Ph.w, Bv[0], Bv[1]);
                mma16816(O[j], Pl.x, Pl.y, Pl.z, Pl.w, Bv[0], Bv[1]);
                mma16816(O[j], Ph.x, Ph.y, Ph.z, Ph.w, Bv[2], Bv[3]);
            }
        }
        __syncthreads();                           // done reading buffer kt&1
    }

    // ---- epilogue: divide by full-row denominator, store ----
    const int row0 = q0 + rg * 16 + g;
    const int row1 = row0 + 8;
    const float i0 = 1.0f / g_d[(size_t)b * NSEQ + row0];
    const float i1 = 1.0f / g_d[(size_t)b * NSEQ + row1];
    const size_t r0o = ((size_t)b * NSEQ + row0) * CMD + cmq * 64;
    const size_t r1o = ((size_t)b * NSEQ + row1) * CMD + cmq * 64;
    #pragma unroll
    for (int j = 0; j < 8; j++) {
        float2 v0, v1;
        v0.x = O[j][0] * i0; v0.y = O[j][1] * i0;
        v1.x = O[j][2] * i1; v1.y = O[j][3] * i1;
        *(float2*)(outg + r0o + 8 * j + 2 * t) = v0;
        *(float2*)(outg + r1o + 8 * j + 2 * t) = v1;
    }
}

// ---------------- launch ----------------
extern "C" void kernel_launch(void* const* d_in, const int* in_sizes, int n_in,
                              void* d_out, int out_size)
{
    const float* q = (const float*)d_in[0];
    const float* k = (const float*)d_in[1];
    const float* v = (const float*)d_in[2];
    float* out = (float*)d_out;

    cudaFuncSetAttribute(s_kernel,
                         cudaFuncAttributeMaxDynamicSharedMemorySize, S_SMEM);
    cudaFuncSetAttribute(pv_kernel,
                         cudaFuncAttributeMaxDynamicSharedMemorySize, PV_SMEM);

    prep_all<<<4096 + 8192, 256>>>(q, k, v);
    s_kernel<<<dim3(16, BATCH), 256, S_SMEM>>>();
    pv_kernel<<<2048, 128, PV_SMEM>>>(out);

    (void)in_sizes; (void)n_in; (void)out_size;
}